// round 6
// baseline (speedup 1.0000x reference)
#include <cuda_runtime.h>
#include <cstdint>

#define B_  8
#define C_  32
#define H_  64
#define W_  64
#define F_  64
#define TH  8                // output rows per CTA
#define NT  128
#define XROWS (TH + 2)       // 10 staged rows (halo)
#define XSTR  68             // padded smem row stride (floats), even => 8B-aligned pairs
#define XS_ELE (XROWS * XSTR)

typedef unsigned long long ull;

// ---- packed f32x2 helpers (sm_10x packed fp32 pipe, PTX-only) ----
__device__ __forceinline__ ull pk2(float lo, float hi) {
    ull r; asm("mov.b64 %0, {%1, %2};" : "=l"(r) : "f"(lo), "f"(hi)); return r;
}
__device__ __forceinline__ void upk2(ull v, float& lo, float& hi) {
    asm("mov.b64 {%0, %1}, %2;" : "=f"(lo), "=f"(hi) : "l"(v));
}
__device__ __forceinline__ ull ffma2(ull a, ull b, ull c) {
    ull d; asm("fma.rn.f32x2 %0, %1, %2, %3;" : "=l"(d) : "l"(a), "l"(b), "l"(c)); return d;
}
__device__ __forceinline__ ull fmul2(ull a, ull b) {
    ull d; asm("mul.rn.f32x2 %0, %1, %2;" : "=l"(d) : "l"(a), "l"(b)); return d;
}
__device__ __forceinline__ ull fadd2(ull a, ull b) {
    ull d; asm("add.rn.f32x2 %0, %1, %2;" : "=l"(d) : "l"(a), "l"(b)); return d;
}
__device__ __forceinline__ ull and64(ull a, ull b) {
    ull d; asm("and.b64 %0, %1, %2;" : "=l"(d) : "l"(a), "l"(b)); return d;
}
__device__ __forceinline__ float frcp(float x) {
    float r; asm("rcp.approx.ftz.f32 %0, %1;" : "=f"(r) : "f"(x)); return r;
}
__device__ __forceinline__ uint32_t s2u32(const void* p) {
    uint32_t a;
    asm("{ .reg .u64 t; cvta.to.shared.u64 t, %1; cvt.u32.u64 %0, t; }"
        : "=r"(a) : "l"(p));
    return a;
}
// cp.async 4B with zfill via src-size (0 => zero-fill destination)
__device__ __forceinline__ void cpa4(uint32_t dst, const float* src, int ssz) {
    asm volatile("cp.async.ca.shared.global [%0], [%1], 4, %2;"
                 :: "r"(dst), "l"(src), "r"(ssz) : "memory");
}
__device__ __forceinline__ void cpa_commit() {
    asm volatile("cp.async.commit_group;" ::: "memory");
}
template <int N>
__device__ __forceinline__ void cpa_wait() {
    asm volatile("cp.async.wait_group %0;" :: "n"(N) : "memory");
}

// Stage one halo'd channel tile x[b,c, h0-1 .. h0+TH, -1..64] (10x66) into smem.
// Warp `wid` takes rows wid+4t; lane covers cols lane, lane+32, (+64 lanes 0,1).
__device__ __forceinline__ void stage_tile(const float* __restrict__ xc, int h0,
                                           uint32_t dstbase, int wid, int lane)
{
    #pragma unroll
    for (int t = 0; t < 3; ++t) {
        int rr = wid + 4 * t;
        if (t < 2 || wid < 2) {            // rr < 10
            int gh = h0 - 1 + rr;
            bool ghv = (gh >= 0) && (gh < H_);
            const float* rowp = xc + (ghv ? gh : 0) * W_;
            uint32_t drow = dstbase + (uint32_t)(rr * XSTR) * 4u;
            {   // cc = lane -> gw = lane-1
                int gw = lane - 1;
                bool v = ghv && (gw >= 0);
                cpa4(drow + lane * 4u, rowp + (v ? gw : 0), v ? 4 : 0);
            }
            {   // cc = lane+32 -> gw = lane+31 (always in range when ghv)
                int gw = lane + 31;
                cpa4(drow + (lane + 32) * 4u, rowp + (ghv ? gw : 0), ghv ? 4 : 0);
            }
            if (lane < 2) {   // cc = 64,65 -> gw = 63 (valid), 64 (zero)
                int gw = lane + 63;
                bool v = ghv && (gw < W_);
                cpa4(drow + (lane + 64) * 4u, rowp + (v ? gw : 0), v ? 4 : 0);
            }
        }
    }
}

__global__ __launch_bounds__(NT, 7)
void kan_kernel(const float* __restrict__ x,
                const float* __restrict__ numc,
                const float* __restrict__ denc,
                float* __restrict__ out)
{
    // coef_s[(tap*32 + c)*10 + j]: j=0..5 num a0..a5, j=6..9 den b1..b4,
    // duplicated into both f32x2 lanes; entry = 80B so 16B-aligned for LDS.128.
    __shared__ __align__(16) ull coef_s[9 * C_ * 10];   // 23040 B
    __shared__ float xs[2][XS_ELE];                      //  5440 B (ping-pong)

    const int tile = blockIdx.x;          // 0..7
    const int f    = blockIdx.y;
    const int b    = blockIdx.z;
    const int h0   = tile * TH;
    const int tid  = threadIdx.x;
    const int wid  = tid >> 5, lane = tid & 31;

    const float* xb_gl = x + (((size_t)b * C_) * H_) * W_;
    const uint32_t xs0 = s2u32(&xs[0][0]);
    const uint32_t xs1 = s2u32(&xs[1][0]);

    // ---- prefetch channel 0 ----
    stage_tile(xb_gl, h0, xs0, wid, lane);
    cpa_commit();

    // ---- stage filter-f coefficients (duplicated f32x2) ----
    {
        const float* np = numc + (size_t)f * 9 * C_ * 6;
        for (int i = tid; i < 9 * C_ * 6; i += NT) {
            int t = i / (C_ * 6);
            int r = i - t * (C_ * 6);
            int c = r / 6, j = r - c * 6;
            float v = np[i];
            coef_s[(t * C_ + c) * 10 + j] = pk2(v, v);
        }
        const float* dp = denc + (size_t)f * 9 * C_ * 4;
        for (int i = tid; i < 9 * C_ * 4; i += NT) {
            int t = i / (C_ * 4);
            int r = i - t * (C_ * 4);
            int c = r / 4, j = r - c * 4;
            float v = dp[i];
            coef_s[(t * C_ + c) * 10 + 6 + j] = pk2(v, v);
        }
    }

    // compute mapping: pair = (row rs+4m, cols 2*lane, 2*lane+1), m = 0..1
    const int rs = wid;                   // 0..3
    const int w2 = lane << 1;             // 0,2,..,62

    const ull ABS2 = 0x7FFFFFFF7FFFFFFFULL;
    const ull ONE2 = pk2(1.0f, 1.0f);

    ull acc0 = 0, acc1 = 0;

    #pragma unroll 1
    for (int c = 0; c < C_; ++c) {
        if (c + 1 < C_) {
            const float* xc1 = xb_gl + (size_t)(c + 1) * H_ * W_;
            stage_tile(xc1, h0, ((c + 1) & 1) ? xs1 : xs0, wid, lane);
            cpa_commit();
            cpa_wait<1>();               // channel c's buffer complete
        } else {
            cpa_wait<0>();
        }
        __syncthreads();                  // all threads' copies visible

        const float* xb = xs[c & 1] + rs * XSTR + w2;

        #pragma unroll
        for (int ta = 0; ta < 3; ta++) {
            // x window for this tap-row: rows rs+4m+ta, cols w2..w2+3
            float2 A0 = *(const float2*)(xb + (ta)     * XSTR);
            float2 B0 = *(const float2*)(xb + (ta)     * XSTR + 2);
            float2 A1 = *(const float2*)(xb + (ta + 4) * XSTR);
            float2 B1 = *(const float2*)(xb + (ta + 4) * XSTR + 2);

            #pragma unroll
            for (int tb = 0; tb < 3; tb++) {
                const ulonglong2* cs2 = reinterpret_cast<const ulonglong2*>(
                    &coef_s[((ta * 3 + tb) * C_ + c) * 10]);
                const ulonglong2 v0 = cs2[0], v1 = cs2[1], v2 = cs2[2],
                                 v3 = cs2[3], v4 = cs2[4];
                const ull a0 = v0.x, a1 = v0.y, a2 = v1.x, a3 = v1.y,
                          a4 = v2.x, a5 = v2.y;
                const ull b1 = v3.x, b2 = v3.y, b3 = v4.x, b4 = v4.y;

                #pragma unroll
                for (int m = 0; m < 2; m++) {
                    const float2 A = m ? A1 : A0;
                    const float2 B = m ? B1 : B0;
                    ull xp = (tb == 0) ? pk2(A.x, A.y)
                           : (tb == 1) ? pk2(A.y, B.x)
                                       : pk2(B.x, B.y);

                    ull num = ffma2(a5, xp, a4);
                    num = ffma2(num, xp, a3);
                    num = ffma2(num, xp, a2);
                    num = ffma2(num, xp, a1);
                    num = ffma2(num, xp, a0);
                    ull q = ffma2(b4, xp, b3);
                    q = ffma2(q, xp, b2);
                    q = ffma2(q, xp, b1);
                    ull t = and64(fmul2(q, xp), ABS2);
                    ull den = fadd2(ONE2, t);

                    float d0, d1; upk2(den, d0, d1);
                    ull inv = pk2(frcp(d0), frcp(d1));
                    if (m) acc1 = ffma2(num, inv, acc1);
                    else   acc0 = ffma2(num, inv, acc0);
                }
            }
        }
        if (c + 1 < C_) __syncthreads();  // readers done before next overwrite
    }

    // ---- write out[b][f][h0+rs+4m][w2..w2+1] as float2 ----
    float* ob = out + (((size_t)b * F_ + f) * H_ + h0) * W_;
    {
        float lo, hi;
        upk2(acc0, lo, hi);
        *(float2*)&ob[(rs)     * W_ + w2] = make_float2(lo, hi);
        upk2(acc1, lo, hi);
        *(float2*)&ob[(rs + 4) * W_ + w2] = make_float2(lo, hi);
    }
}

extern "C" void kernel_launch(void* const* d_in, const int* in_sizes, int n_in,
                              void* d_out, int out_size)
{
    const float* x  = (const float*)d_in[0];
    const float* nc = (const float*)d_in[1];
    const float* dc = (const float*)d_in[2];
    float* out = (float*)d_out;

    dim3 grid(H_ / TH, F_, B_);   // 8 x 64 x 8 = 4096 CTAs
    kan_kernel<<<grid, NT>>>(x, nc, dc, out);
}